// round 14
// baseline (speedup 1.0000x reference)
#include <cuda_runtime.h>
#include <math.h>
#include <stdint.h>

// Problem constants
#define BATCH   8
#define SEQ     2048
#define HID     1024
#define VEC_PB  (SEQ * HID / 4)    // 524,288 float4 per batch
#define TOTALV  (BATCH * VEC_PB)   // 4,194,304 float4 total
#define RANK0   1048576u           // 0-indexed ascending rank of threshold (N - k)
#define NB0     8192               // pass-0 bins: bits[30:18]
#define NB1     2048               // pass-1 bins: bits[17:7]
#define NSEG    32                 // segments per batch (64 rows each)
#define NBLK    (NSEG * BATCH)     // 256 blocks — co-resident with 2x margin
#define ROWS    64                 // rows per segment (band-aligned: 64 | 128)

// Static scratch (zero-initialized at module load; every launch restores the
// zero state it consumed, so graph replays are deterministic)
__device__ __align__(16) float g_imp5[5 * HID];
__device__ unsigned g_hist0[BATCH][NB0];     // 256 KB
__device__ unsigned g_hist1[BATCH][NB1];     // 64 KB
__device__ unsigned g_d0[BATCH];
__device__ unsigned g_r1[BATCH];
__device__ float    g_thr[BATCH];
__device__ unsigned g_bar[5];                // grid barrier slots (cyclic reset)

__device__ __forceinline__ float sigmoidf_fast(float x) {
    return 1.0f / (1.0f + __expf(-x));
}

// band(t): 0 for t<128, else floor(log2(t>>7)) + 1   (T=2048, L=4)
__device__ __forceinline__ int band_of(int t) {
    return (t >= 128) ? (32 - __clz(t >> 7)) : 0;
}

// Grid-wide spin barrier over 5 single-use slots.
// Residency: 256 blocks need only 2 blocks/SM (smem allows 6, regs allow 8).
// Each passage zeroes slot (p+2)%5: stale slots from the previous replay are
// cleared >=2 barriers before their arrivals this replay; the fence orders the
// reset before this block's arrival, and barrier completion orders all resets
// before any arrival at the reset slot.
__device__ __forceinline__ void grid_barrier(int p) {
    __syncthreads();
    if (threadIdx.x == 0) {
        *((volatile unsigned*)&g_bar[(p + 2) % 5]) = 0;
        __threadfence();
        atomicAdd(&g_bar[p], 1u);
        while (*((volatile unsigned*)&g_bar[p]) < NBLK) __nanosleep(128);
        __threadfence();
    }
    __syncthreads();
}

// block-collective (256 threads) select over 256*PER bins; the thread owning
// the rank writes dig/rem through the given pointers. __syncthreads at end.
template <int PER>
__device__ __forceinline__ void block_select(const unsigned* __restrict__ h,
                                             unsigned rank,
                                             unsigned* out_dig, unsigned* out_rem,
                                             unsigned* swtot) {
    const int tid = threadIdx.x;
    const int lane = tid & 31;
    const int wid = tid >> 5;

    unsigned s = 0;
    #pragma unroll
    for (int j = 0; j < PER; j++) s += __ldcg(&h[tid * PER + j]);

    unsigned v = s;
    #pragma unroll
    for (int o = 1; o < 32; o <<= 1) {
        unsigned t = __shfl_up_sync(0xFFFFFFFFu, v, o);
        if (lane >= o) v += t;
    }
    if (lane == 31) swtot[wid] = v;
    __syncthreads();

    if (wid == 0 && lane < 8) {
        unsigned t = swtot[lane];
        #pragma unroll
        for (int o = 1; o < 8; o <<= 1) {
            unsigned u = __shfl_up_sync(0xFFu, t, o);
            if (lane >= o) t += u;
        }
        swtot[lane] = t;
    }
    __syncthreads();

    unsigned excl = (wid ? swtot[wid - 1] : 0u) + (v - s);
    if (rank >= excl && rank < excl + s) {
        unsigned cum = excl;
        #pragma unroll 1
        for (int j = 0; j < PER; j++) {
            unsigned c = __ldcg(&h[tid * PER + j]);
            if (rank < cum + c) {
                *out_dig = (unsigned)(tid * PER + j);
                *out_rem = rank - cum;
                break;
            }
            cum += c;
        }
    }
    __syncthreads();
}

// ---------------------------------------------------------------------------
// The whole pipeline in one persistent kernel.
// Block bx: batch = bx>>5, seg = bx&31, rows [seg*64, seg*64+64) (one band).
// ---------------------------------------------------------------------------
__global__ void __launch_bounds__(256, 4)
filter_kernel(const float4* __restrict__ coeffs,
              const float* __restrict__ bi,
              const float* __restrict__ di,
              const float* __restrict__ temp,
              float4* __restrict__ out) {
    __shared__ unsigned sh[NB0];     // 32 KB: hist0, reused as hist1[0..NB1)
    __shared__ unsigned swtot[8];
    __shared__ unsigned s_d1, s_r2;

    const int tid = threadIdx.x;
    const int bx = blockIdx.x;
    const int batch = bx >> 5;
    const int seg = bx & 31;
    const int band = band_of(seg << 6);   // 64 rows/seg; boundaries at mult of 64

    // ---- P0: build importance table (blocks 0..19 cover 5*HID entries) ----
    if (bx < 20) {
        int i = bx * 256 + tid;          // < 5120 == 5*HID
        float sb = sigmoidf_fast(__ldg(&bi[i]));
        float sd = sigmoidf_fast(__ldg(&di[i & (HID - 1)]));
        g_imp5[i] = sb * sd;
    }
    grid_barrier(0);

    const float4 imp = *reinterpret_cast<const float4*>(&g_imp5[band * HID + (tid << 2)]);
    const float4* p = coeffs + (size_t)batch * VEC_PB + (size_t)seg * (ROWS * 256) + tid;

    // ---- A: hist0 on bits[30:18] (8192 bins; conflicts ~1-2, no replicas) ----
    for (int i = tid; i < NB0; i += 256) sh[i] = 0;
    __syncthreads();

    #pragma unroll 2
    for (int r = 0; r < ROWS; r += 4) {
        float4 c0 = __ldg(p + (r + 0) * 256);
        float4 c1 = __ldg(p + (r + 1) * 256);
        float4 c2 = __ldg(p + (r + 2) * 256);
        float4 c3 = __ldg(p + (r + 3) * 256);
        atomicAdd(&sh[__float_as_uint(imp.x * fabsf(c0.x)) >> 18], 1u);
        atomicAdd(&sh[__float_as_uint(imp.y * fabsf(c0.y)) >> 18], 1u);
        atomicAdd(&sh[__float_as_uint(imp.z * fabsf(c0.z)) >> 18], 1u);
        atomicAdd(&sh[__float_as_uint(imp.w * fabsf(c0.w)) >> 18], 1u);
        atomicAdd(&sh[__float_as_uint(imp.x * fabsf(c1.x)) >> 18], 1u);
        atomicAdd(&sh[__float_as_uint(imp.y * fabsf(c1.y)) >> 18], 1u);
        atomicAdd(&sh[__float_as_uint(imp.z * fabsf(c1.z)) >> 18], 1u);
        atomicAdd(&sh[__float_as_uint(imp.w * fabsf(c1.w)) >> 18], 1u);
        atomicAdd(&sh[__float_as_uint(imp.x * fabsf(c2.x)) >> 18], 1u);
        atomicAdd(&sh[__float_as_uint(imp.y * fabsf(c2.y)) >> 18], 1u);
        atomicAdd(&sh[__float_as_uint(imp.z * fabsf(c2.z)) >> 18], 1u);
        atomicAdd(&sh[__float_as_uint(imp.w * fabsf(c2.w)) >> 18], 1u);
        atomicAdd(&sh[__float_as_uint(imp.x * fabsf(c3.x)) >> 18], 1u);
        atomicAdd(&sh[__float_as_uint(imp.y * fabsf(c3.y)) >> 18], 1u);
        atomicAdd(&sh[__float_as_uint(imp.z * fabsf(c3.z)) >> 18], 1u);
        atomicAdd(&sh[__float_as_uint(imp.w * fabsf(c3.w)) >> 18], 1u);
    }
    __syncthreads();

    {
        unsigned* gh = g_hist0[batch];
        for (int i = tid; i < NB0; i += 256) {
            unsigned s = sh[i];
            if (s) atomicAdd(&gh[i], s);
        }
    }
    grid_barrier(1);

    // ---- B: select0 (blocks 0..7, one per batch), then re-zero hist0 ----
    if (bx < BATCH) {
        block_select<NB0 / 256>(g_hist0[bx], RANK0, &g_d0[bx], &g_r1[bx], swtot);
        for (int i = tid; i < NB0; i += 256) g_hist0[bx][i] = 0;
    }
    grid_barrier(2);

    // ---- C: hist1 on bits[17:7] among prefix-matching values (L2-fed reads) ----
    for (int i = tid; i < NB1; i += 256) sh[i] = 0;
    __syncthreads();

    const unsigned pref = __ldcg(&g_d0[batch]);
    #pragma unroll 2
    for (int r = 0; r < ROWS; r += 4) {
        float4 c0 = __ldg(p + (r + 0) * 256);
        float4 c1 = __ldg(p + (r + 1) * 256);
        float4 c2 = __ldg(p + (r + 2) * 256);
        float4 c3 = __ldg(p + (r + 3) * 256);
        unsigned bb[16];
        bb[0]  = __float_as_uint(imp.x * fabsf(c0.x));
        bb[1]  = __float_as_uint(imp.y * fabsf(c0.y));
        bb[2]  = __float_as_uint(imp.z * fabsf(c0.z));
        bb[3]  = __float_as_uint(imp.w * fabsf(c0.w));
        bb[4]  = __float_as_uint(imp.x * fabsf(c1.x));
        bb[5]  = __float_as_uint(imp.y * fabsf(c1.y));
        bb[6]  = __float_as_uint(imp.z * fabsf(c1.z));
        bb[7]  = __float_as_uint(imp.w * fabsf(c1.w));
        bb[8]  = __float_as_uint(imp.x * fabsf(c2.x));
        bb[9]  = __float_as_uint(imp.y * fabsf(c2.y));
        bb[10] = __float_as_uint(imp.z * fabsf(c2.z));
        bb[11] = __float_as_uint(imp.w * fabsf(c2.w));
        bb[12] = __float_as_uint(imp.x * fabsf(c3.x));
        bb[13] = __float_as_uint(imp.y * fabsf(c3.y));
        bb[14] = __float_as_uint(imp.z * fabsf(c3.z));
        bb[15] = __float_as_uint(imp.w * fabsf(c3.w));
        #pragma unroll
        for (int j = 0; j < 16; j++)
            if ((bb[j] >> 18) == pref) atomicAdd(&sh[(bb[j] >> 7) & (NB1 - 1)], 1u);
    }
    __syncthreads();

    {
        unsigned* gh = g_hist1[batch];
        for (int i = tid; i < NB1; i += 256) {
            unsigned s = sh[i];
            if (s) atomicAdd(&gh[i], s);
        }
    }
    grid_barrier(3);

    // ---- D: select1 -> threshold (midpoint of 128-ulp bin, rel err <= 2^-17),
    //         then re-zero hist1 ----
    if (bx < BATCH) {
        block_select<NB1 / 256>(g_hist1[bx], __ldcg(&g_r1[bx]), &s_d1, &s_r2, swtot);
        if (tid == 0)
            g_thr[bx] = __uint_as_float((__ldcg(&g_d0[bx]) << 18) | (s_d1 << 7) | 64u);
        __syncthreads();
        for (int i = tid; i < NB1; i += 256) g_hist1[bx][i] = 0;
    }
    grid_barrier(4);

    // ---- E: final outputs (coeffs reads L2-resident; 192MB streamed out) ----
    const float thr = __ldcg(&g_thr[batch]);
    const float inv_t = __frcp_rn(fabsf(__ldg(&temp[0])));
    const size_t vbase = (size_t)batch * VEC_PB + (size_t)seg * (ROWS * 256) + tid;

    #pragma unroll 2
    for (int r = 0; r < ROWS; r += 2) {
        float4 c0 = __ldg(p + (r + 0) * 256);
        float4 c1 = __ldg(p + (r + 1) * 256);

        float4 mk0, fl0, mk1, fl1;
        { float ci = imp.x * fabsf(c0.x); mk0.x = sigmoidf_fast((ci - thr) * inv_t); fl0.x = c0.x * mk0.x; }
        { float ci = imp.y * fabsf(c0.y); mk0.y = sigmoidf_fast((ci - thr) * inv_t); fl0.y = c0.y * mk0.y; }
        { float ci = imp.z * fabsf(c0.z); mk0.z = sigmoidf_fast((ci - thr) * inv_t); fl0.z = c0.z * mk0.z; }
        { float ci = imp.w * fabsf(c0.w); mk0.w = sigmoidf_fast((ci - thr) * inv_t); fl0.w = c0.w * mk0.w; }
        { float ci = imp.x * fabsf(c1.x); mk1.x = sigmoidf_fast((ci - thr) * inv_t); fl1.x = c1.x * mk1.x; }
        { float ci = imp.y * fabsf(c1.y); mk1.y = sigmoidf_fast((ci - thr) * inv_t); fl1.y = c1.y * mk1.y; }
        { float ci = imp.z * fabsf(c1.z); mk1.z = sigmoidf_fast((ci - thr) * inv_t); fl1.z = c1.z * mk1.z; }
        { float ci = imp.w * fabsf(c1.w); mk1.w = sigmoidf_fast((ci - thr) * inv_t); fl1.w = c1.w * mk1.w; }

        size_t ve0 = vbase + (size_t)(r + 0) * 256;
        size_t ve1 = vbase + (size_t)(r + 1) * 256;
        __stcs(&out[ve0], fl0);
        __stcs(&out[ve1], fl1);
        __stcs(&out[TOTALV + ve0], mk0);
        __stcs(&out[TOTALV + ve1], mk1);
        __stcs(&out[2 * TOTALV + ve0], imp);
        __stcs(&out[2 * TOTALV + ve1], imp);
    }
}

// ---------------------------------------------------------------------------
// launch — ONE kernel
// ---------------------------------------------------------------------------
extern "C" void kernel_launch(void* const* d_in, const int* in_sizes, int n_in,
                              void* d_out, int out_size) {
    const float* coeffs = (const float*)d_in[0];
    const float* bi     = (const float*)d_in[1];
    const float* di     = (const float*)d_in[2];
    const float* temp   = (const float*)d_in[3];
    float* out = (float*)d_out;

    filter_kernel<<<NBLK, 256>>>((const float4*)coeffs, bi, di, temp, (float4*)out);
}

// round 16
// speedup vs baseline: 1.0678x; 1.0678x over previous
#include <cuda_runtime.h>
#include <math.h>
#include <stdint.h>

// Problem constants
#define BATCH   8
#define SEQ     2048
#define HID     1024
#define VEC_PB  (SEQ * HID / 4)    // 524,288 float4 per batch
#define TOTALV  (BATCH * VEC_PB)   // 4,194,304 float4 total
#define RANK0   1048576u           // 0-indexed ascending rank of threshold (N - k)
#define NB0     8192               // pass-0 bins: bits[30:18] (sign always 0)
#define NB1     2048               // pass-1 bins: bits[17:7]
#define HBLK    128                // hist blocks per batch (16 rows each)
#define FBLK    256                // final blocks per batch (8 rows each)

// Static scratch (no runtime allocation allowed)
__device__ __align__(16) float g_imp5[5 * HID];   // sigmoid(band)*sigmoid(dim)
__device__ unsigned g_hist0[BATCH][NB0];          // 256 KB
__device__ unsigned g_hist1[BATCH][NB1];          // 64 KB
__device__ unsigned g_d0[BATCH];                  // selected 13-bit digit, pass 0
__device__ unsigned g_r1[BATCH];                  // remaining rank after pass 0
__device__ float    g_thr[BATCH];

__device__ __forceinline__ float sigmoidf_fast(float x) {
    return 1.0f / (1.0f + __expf(-x));
}

// band(t): 0 for t<128, else floor(log2(t>>7)) + 1   (T=2048, L=4)
__device__ __forceinline__ int band_of(int t) {
    return (t >= 128) ? (32 - __clz(t >> 7)) : 0;
}

// ---------------------------------------------------------------------------
// setup: zero both histograms, build importance table
// ---------------------------------------------------------------------------
__global__ void setup_kernel(const float* __restrict__ bi, const float* __restrict__ di) {
    int i = blockIdx.x * blockDim.x + threadIdx.x;
    if (i < BATCH * NB0) ((unsigned*)g_hist0)[i] = 0;
    if (i < BATCH * NB1) ((unsigned*)g_hist1)[i] = 0;
    if (i < 5 * HID) {
        float sb = sigmoidf_fast(bi[i]);
        float sd = sigmoidf_fast(di[i & (HID - 1)]);
        g_imp5[i] = sb * sd;
    }
}

// ---------------------------------------------------------------------------
// pass 0: histogram bits[30:18] (8192 bins; hot exponent mass spread over 32
// mantissa sub-bins -> intra-warp conflicts ~1-2 -> no replicas) AND stream
// the importance_map output (imp is a register constant; writes use the
// otherwise-idle store path). grid (HBLK, BATCH) x 256; block = 16 rows.
// ---------------------------------------------------------------------------
__global__ void __launch_bounds__(256) hist0_kernel(const float4* __restrict__ coeffs,
                                                    float4* __restrict__ out) {
    __shared__ unsigned sh[NB0];                 // 32 KB
    const int tid = threadIdx.x;

    for (int i = tid; i < NB0; i += 256) sh[i] = 0;
    __syncthreads();

    const int batch = blockIdx.y;
    const int band = band_of(blockIdx.x << 4);
    const float4 imp = *reinterpret_cast<const float4*>(&g_imp5[band * HID + (tid << 2)]);
    const size_t vbase = (size_t)batch * VEC_PB + (size_t)blockIdx.x * (16 * 256) + tid;
    const float4* p = coeffs + vbase;
    float4* iout = out + 2 * TOTALV + vbase;

    #pragma unroll
    for (int r = 0; r < 16; r += 4) {
        float4 c0 = __ldg(p + (r + 0) * 256);
        float4 c1 = __ldg(p + (r + 1) * 256);
        float4 c2 = __ldg(p + (r + 2) * 256);
        float4 c3 = __ldg(p + (r + 3) * 256);
        __stcs(iout + (r + 0) * 256, imp);
        __stcs(iout + (r + 1) * 256, imp);
        __stcs(iout + (r + 2) * 256, imp);
        __stcs(iout + (r + 3) * 256, imp);
        atomicAdd(&sh[__float_as_uint(imp.x * fabsf(c0.x)) >> 18], 1u);
        atomicAdd(&sh[__float_as_uint(imp.y * fabsf(c0.y)) >> 18], 1u);
        atomicAdd(&sh[__float_as_uint(imp.z * fabsf(c0.z)) >> 18], 1u);
        atomicAdd(&sh[__float_as_uint(imp.w * fabsf(c0.w)) >> 18], 1u);
        atomicAdd(&sh[__float_as_uint(imp.x * fabsf(c1.x)) >> 18], 1u);
        atomicAdd(&sh[__float_as_uint(imp.y * fabsf(c1.y)) >> 18], 1u);
        atomicAdd(&sh[__float_as_uint(imp.z * fabsf(c1.z)) >> 18], 1u);
        atomicAdd(&sh[__float_as_uint(imp.w * fabsf(c1.w)) >> 18], 1u);
        atomicAdd(&sh[__float_as_uint(imp.x * fabsf(c2.x)) >> 18], 1u);
        atomicAdd(&sh[__float_as_uint(imp.y * fabsf(c2.y)) >> 18], 1u);
        atomicAdd(&sh[__float_as_uint(imp.z * fabsf(c2.z)) >> 18], 1u);
        atomicAdd(&sh[__float_as_uint(imp.w * fabsf(c2.w)) >> 18], 1u);
        atomicAdd(&sh[__float_as_uint(imp.x * fabsf(c3.x)) >> 18], 1u);
        atomicAdd(&sh[__float_as_uint(imp.y * fabsf(c3.y)) >> 18], 1u);
        atomicAdd(&sh[__float_as_uint(imp.z * fabsf(c3.z)) >> 18], 1u);
        atomicAdd(&sh[__float_as_uint(imp.w * fabsf(c3.w)) >> 18], 1u);
    }
    __syncthreads();

    unsigned* gh = g_hist0[batch];
    for (int i = tid; i < NB0; i += 256) {
        unsigned s = sh[i];
        if (s) atomicAdd(&gh[i], s);
    }
}

// ---------------------------------------------------------------------------
// select0: one block of 256 threads per batch over 8192 bins.
// ---------------------------------------------------------------------------
__global__ void __launch_bounds__(256) select0_kernel() {
    __shared__ unsigned wtot[8];
    const int b = blockIdx.x;
    const int tid = threadIdx.x;
    const int lane = tid & 31;
    const int wid = tid >> 5;
    const unsigned* __restrict__ h = g_hist0[b];

    unsigned s = 0;
    #pragma unroll
    for (int j = 0; j < 32; j++) s += __ldcg(&h[tid * 32 + j]);

    unsigned v = s;
    #pragma unroll
    for (int o = 1; o < 32; o <<= 1) {
        unsigned t = __shfl_up_sync(0xFFFFFFFFu, v, o);
        if (lane >= o) v += t;
    }
    if (lane == 31) wtot[wid] = v;
    __syncthreads();

    if (wid == 0 && lane < 8) {
        unsigned t = wtot[lane];
        #pragma unroll
        for (int o = 1; o < 8; o <<= 1) {
            unsigned u = __shfl_up_sync(0xFFu, t, o);
            if (lane >= o) t += u;
        }
        wtot[lane] = t;
    }
    __syncthreads();

    unsigned excl = (wid ? wtot[wid - 1] : 0u) + (v - s);
    if (RANK0 >= excl && RANK0 < excl + s) {
        unsigned cum = excl;
        #pragma unroll 1
        for (int j = 0; j < 32; j++) {
            unsigned c = __ldcg(&h[tid * 32 + j]);
            if (RANK0 < cum + c) {
                g_d0[b] = (unsigned)(tid * 32 + j);
                g_r1[b] = RANK0 - cum;
                break;
            }
            cum += c;
        }
    }
}

// ---------------------------------------------------------------------------
// pass 1: histogram bits[17:7] among values with bits[30:18] == d0
// (~1% match -> atomics negligible). Reads likely L2-hit after hist0.
// ---------------------------------------------------------------------------
__global__ void __launch_bounds__(256) hist1_kernel(const float4* __restrict__ coeffs) {
    __shared__ unsigned sh[NB1];
    const int tid = threadIdx.x;

    for (int i = tid; i < NB1; i += 256) sh[i] = 0;
    __syncthreads();

    const int batch = blockIdx.y;
    const unsigned pref = g_d0[batch];
    const int band = band_of(blockIdx.x << 4);
    const float4 imp = *reinterpret_cast<const float4*>(&g_imp5[band * HID + (tid << 2)]);
    const float4* p = coeffs + (size_t)batch * VEC_PB + (size_t)blockIdx.x * (16 * 256) + tid;

    #pragma unroll
    for (int r = 0; r < 16; r += 4) {
        float4 c0 = __ldg(p + (r + 0) * 256);
        float4 c1 = __ldg(p + (r + 1) * 256);
        float4 c2 = __ldg(p + (r + 2) * 256);
        float4 c3 = __ldg(p + (r + 3) * 256);
        unsigned bb[16];
        bb[0]  = __float_as_uint(imp.x * fabsf(c0.x));
        bb[1]  = __float_as_uint(imp.y * fabsf(c0.y));
        bb[2]  = __float_as_uint(imp.z * fabsf(c0.z));
        bb[3]  = __float_as_uint(imp.w * fabsf(c0.w));
        bb[4]  = __float_as_uint(imp.x * fabsf(c1.x));
        bb[5]  = __float_as_uint(imp.y * fabsf(c1.y));
        bb[6]  = __float_as_uint(imp.z * fabsf(c1.z));
        bb[7]  = __float_as_uint(imp.w * fabsf(c1.w));
        bb[8]  = __float_as_uint(imp.x * fabsf(c2.x));
        bb[9]  = __float_as_uint(imp.y * fabsf(c2.y));
        bb[10] = __float_as_uint(imp.z * fabsf(c2.z));
        bb[11] = __float_as_uint(imp.w * fabsf(c2.w));
        bb[12] = __float_as_uint(imp.x * fabsf(c3.x));
        bb[13] = __float_as_uint(imp.y * fabsf(c3.y));
        bb[14] = __float_as_uint(imp.z * fabsf(c3.z));
        bb[15] = __float_as_uint(imp.w * fabsf(c3.w));
        #pragma unroll
        for (int j = 0; j < 16; j++)
            if ((bb[j] >> 18) == pref) atomicAdd(&sh[(bb[j] >> 7) & (NB1 - 1)], 1u);
    }
    __syncthreads();

    unsigned* gh = g_hist1[batch];
    for (int i = tid; i < NB1; i += 256) {
        unsigned s = sh[i];
        if (s) atomicAdd(&gh[i], s);
    }
}

// ---------------------------------------------------------------------------
// select1: one warp per batch; threshold = midpoint of resolved 128-ulp bin
// (rel err <= 2^-17; measured end-to-end rel_err 5e-7).
// ---------------------------------------------------------------------------
__global__ void __launch_bounds__(256) select1_kernel() {
    const int b = threadIdx.x >> 5;
    if (b >= BATCH) return;
    const int lane = threadIdx.x & 31;
    const unsigned* __restrict__ h = g_hist1[b];
    const unsigned rank = g_r1[b];

    unsigned s = 0;
    #pragma unroll
    for (int j = 0; j < 64; j++) s += __ldcg(&h[lane * 64 + j]);

    unsigned v = s;
    #pragma unroll
    for (int o = 1; o < 32; o <<= 1) {
        unsigned t = __shfl_up_sync(0xFFFFFFFFu, v, o);
        if (lane >= o) v += t;
    }
    unsigned excl = v - s;

    if (rank >= excl && rank < excl + s) {
        unsigned cum = excl;
        #pragma unroll 1
        for (int j = 0; j < 64; j++) {
            unsigned c = __ldcg(&h[lane * 64 + j]);
            if (rank < cum + c) {
                unsigned d1 = (unsigned)(lane * 64 + j);
                g_thr[b] = __uint_as_float((g_d0[b] << 18) | (d1 << 7) | 64u);
                break;
            }
            cum += c;
        }
    }
}

// ---------------------------------------------------------------------------
// final: out[0..V)=coeffs*mask, out[V..2V)=mask. (importance already written
// by hist0.) grid (FBLK, BATCH) x 256: 8 rows/block. Streaming stores.
// ---------------------------------------------------------------------------
__global__ void __launch_bounds__(256) final_kernel(const float4* __restrict__ coeffs,
                                                    const float* __restrict__ temp,
                                                    float4* __restrict__ out) {
    const int tid = threadIdx.x;
    const int batch = blockIdx.y;
    const int band = band_of(blockIdx.x << 3);   // 8 rows/block
    const float4 imp = *reinterpret_cast<const float4*>(&g_imp5[band * HID + (tid << 2)]);
    const float thr = g_thr[batch];
    const float inv_t = __frcp_rn(fabsf(__ldg(&temp[0])));

    const size_t vbase = (size_t)batch * VEC_PB + (size_t)blockIdx.x * (8 * 256) + tid;
    const float4* p = coeffs + vbase;

    #pragma unroll
    for (int r = 0; r < 8; r += 2) {
        float4 c0 = __ldg(p + (r + 0) * 256);
        float4 c1 = __ldg(p + (r + 1) * 256);

        float4 mk0, fl0, mk1, fl1;
        { float ci = imp.x * fabsf(c0.x); mk0.x = sigmoidf_fast((ci - thr) * inv_t); fl0.x = c0.x * mk0.x; }
        { float ci = imp.y * fabsf(c0.y); mk0.y = sigmoidf_fast((ci - thr) * inv_t); fl0.y = c0.y * mk0.y; }
        { float ci = imp.z * fabsf(c0.z); mk0.z = sigmoidf_fast((ci - thr) * inv_t); fl0.z = c0.z * mk0.z; }
        { float ci = imp.w * fabsf(c0.w); mk0.w = sigmoidf_fast((ci - thr) * inv_t); fl0.w = c0.w * mk0.w; }
        { float ci = imp.x * fabsf(c1.x); mk1.x = sigmoidf_fast((ci - thr) * inv_t); fl1.x = c1.x * mk1.x; }
        { float ci = imp.y * fabsf(c1.y); mk1.y = sigmoidf_fast((ci - thr) * inv_t); fl1.y = c1.y * mk1.y; }
        { float ci = imp.z * fabsf(c1.z); mk1.z = sigmoidf_fast((ci - thr) * inv_t); fl1.z = c1.z * mk1.z; }
        { float ci = imp.w * fabsf(c1.w); mk1.w = sigmoidf_fast((ci - thr) * inv_t); fl1.w = c1.w * mk1.w; }

        size_t ve0 = vbase + (size_t)(r + 0) * 256;
        size_t ve1 = vbase + (size_t)(r + 1) * 256;
        __stcs(&out[ve0], fl0);
        __stcs(&out[ve1], fl1);
        __stcs(&out[TOTALV + ve0], mk0);
        __stcs(&out[TOTALV + ve1], mk1);
    }
}

// ---------------------------------------------------------------------------
// launch
// ---------------------------------------------------------------------------
extern "C" void kernel_launch(void* const* d_in, const int* in_sizes, int n_in,
                              void* d_out, int out_size) {
    const float* coeffs = (const float*)d_in[0];
    const float* bi     = (const float*)d_in[1];
    const float* di     = (const float*)d_in[2];
    const float* temp   = (const float*)d_in[3];
    float* out = (float*)d_out;

    setup_kernel<<<(BATCH * NB0 + 255) / 256, 256>>>(bi, di);

    dim3 hg(HBLK, BATCH);
    hist0_kernel<<<hg, 256>>>((const float4*)coeffs, (float4*)out);
    select0_kernel<<<BATCH, 256>>>();
    hist1_kernel<<<hg, 256>>>((const float4*)coeffs);
    select1_kernel<<<1, 256>>>();

    dim3 fg(FBLK, BATCH);
    final_kernel<<<fg, 256>>>((const float4*)coeffs, temp, (float4*)out);
}

// round 17
// speedup vs baseline: 1.0834x; 1.0147x over previous
#include <cuda_runtime.h>
#include <math.h>
#include <stdint.h>

// Problem constants
#define BATCH   8
#define SEQ     2048
#define HID     1024
#define VEC_PB  (SEQ * HID / 4)    // 524,288 float4 per batch
#define TOTALV  (BATCH * VEC_PB)   // 4,194,304 float4 total
#define RANK0   1048576u           // 0-indexed ascending rank of threshold (N - k)
#define NB0     8192               // pass-0 bins: bits[30:18] (sign always 0)
#define NB1     2048               // pass-1 bins: bits[17:7]
#define HBLK    128                // hist blocks per batch (16 rows each)
#define FBLK    256                // final blocks per batch (8 rows each)

// Static scratch (no runtime allocation allowed)
__device__ __align__(16) float g_imp5[5 * HID];   // sigmoid(band)*sigmoid(dim)
__device__ unsigned g_hist0[BATCH][NB0];          // 256 KB
__device__ unsigned g_hist1[BATCH][NB1];          // 64 KB
__device__ unsigned g_d0[BATCH];                  // selected 13-bit digit, pass 0
__device__ unsigned g_r1[BATCH];                  // remaining rank after pass 0
__device__ float    g_thr[BATCH];

// PDL: block until the previous (programmatically serialized) launch completes.
__device__ __forceinline__ void pdl_wait() {
    asm volatile("griddepcontrol.wait;" ::: "memory");
}

__device__ __forceinline__ float sigmoidf_fast(float x) {
    return 1.0f / (1.0f + __expf(-x));
}

// band(t): 0 for t<128, else floor(log2(t>>7)) + 1   (T=2048, L=4)
__device__ __forceinline__ int band_of(int t) {
    return (t >= 128) ? (32 - __clz(t >> 7)) : 0;
}

// ---------------------------------------------------------------------------
// setup: zero both histograms, build importance table
// ---------------------------------------------------------------------------
__global__ void setup_kernel(const float* __restrict__ bi, const float* __restrict__ di) {
    int i = blockIdx.x * blockDim.x + threadIdx.x;
    if (i < BATCH * NB0) ((unsigned*)g_hist0)[i] = 0;
    if (i < BATCH * NB1) ((unsigned*)g_hist1)[i] = 0;
    if (i < 5 * HID) {
        float sb = sigmoidf_fast(bi[i]);
        float sd = sigmoidf_fast(di[i & (HID - 1)]);
        g_imp5[i] = sb * sd;
    }
}

// ---------------------------------------------------------------------------
// pass 0: histogram bits[30:18] (8192 bins; conflict-free) AND stream the
// importance_map output. grid (HBLK, BATCH) x 256; block = 16 rows.
// PDL: smem zeroing overlaps setup_kernel's tail; wait before reading g_imp5.
// ---------------------------------------------------------------------------
__global__ void __launch_bounds__(256) hist0_kernel(const float4* __restrict__ coeffs,
                                                    float4* __restrict__ out) {
    __shared__ unsigned sh[NB0];                 // 32 KB
    const int tid = threadIdx.x;

    for (int i = tid; i < NB0; i += 256) sh[i] = 0;
    pdl_wait();                                  // setup done: g_imp5 + g_hist0 valid
    __syncthreads();

    const int batch = blockIdx.y;
    const int band = band_of(blockIdx.x << 4);
    const float4 imp = *reinterpret_cast<const float4*>(&g_imp5[band * HID + (tid << 2)]);
    const size_t vbase = (size_t)batch * VEC_PB + (size_t)blockIdx.x * (16 * 256) + tid;
    const float4* p = coeffs + vbase;
    float4* iout = out + 2 * TOTALV + vbase;

    #pragma unroll
    for (int r = 0; r < 16; r += 4) {
        float4 c0 = __ldg(p + (r + 0) * 256);
        float4 c1 = __ldg(p + (r + 1) * 256);
        float4 c2 = __ldg(p + (r + 2) * 256);
        float4 c3 = __ldg(p + (r + 3) * 256);
        __stcs(iout + (r + 0) * 256, imp);
        __stcs(iout + (r + 1) * 256, imp);
        __stcs(iout + (r + 2) * 256, imp);
        __stcs(iout + (r + 3) * 256, imp);
        atomicAdd(&sh[__float_as_uint(imp.x * fabsf(c0.x)) >> 18], 1u);
        atomicAdd(&sh[__float_as_uint(imp.y * fabsf(c0.y)) >> 18], 1u);
        atomicAdd(&sh[__float_as_uint(imp.z * fabsf(c0.z)) >> 18], 1u);
        atomicAdd(&sh[__float_as_uint(imp.w * fabsf(c0.w)) >> 18], 1u);
        atomicAdd(&sh[__float_as_uint(imp.x * fabsf(c1.x)) >> 18], 1u);
        atomicAdd(&sh[__float_as_uint(imp.y * fabsf(c1.y)) >> 18], 1u);
        atomicAdd(&sh[__float_as_uint(imp.z * fabsf(c1.z)) >> 18], 1u);
        atomicAdd(&sh[__float_as_uint(imp.w * fabsf(c1.w)) >> 18], 1u);
        atomicAdd(&sh[__float_as_uint(imp.x * fabsf(c2.x)) >> 18], 1u);
        atomicAdd(&sh[__float_as_uint(imp.y * fabsf(c2.y)) >> 18], 1u);
        atomicAdd(&sh[__float_as_uint(imp.z * fabsf(c2.z)) >> 18], 1u);
        atomicAdd(&sh[__float_as_uint(imp.w * fabsf(c2.w)) >> 18], 1u);
        atomicAdd(&sh[__float_as_uint(imp.x * fabsf(c3.x)) >> 18], 1u);
        atomicAdd(&sh[__float_as_uint(imp.y * fabsf(c3.y)) >> 18], 1u);
        atomicAdd(&sh[__float_as_uint(imp.z * fabsf(c3.z)) >> 18], 1u);
        atomicAdd(&sh[__float_as_uint(imp.w * fabsf(c3.w)) >> 18], 1u);
    }
    __syncthreads();

    unsigned* gh = g_hist0[batch];
    for (int i = tid; i < NB0; i += 256) {
        unsigned s = sh[i];
        if (s) atomicAdd(&gh[i], s);
    }
}

// ---------------------------------------------------------------------------
// select0: one block of 256 threads per batch over 8192 bins.
// ---------------------------------------------------------------------------
__global__ void __launch_bounds__(256) select0_kernel() {
    __shared__ unsigned wtot[8];
    pdl_wait();                                  // hist0 done: g_hist0 valid
    const int b = blockIdx.x;
    const int tid = threadIdx.x;
    const int lane = tid & 31;
    const int wid = tid >> 5;
    const unsigned* __restrict__ h = g_hist0[b];

    unsigned s = 0;
    #pragma unroll
    for (int j = 0; j < 32; j++) s += __ldcg(&h[tid * 32 + j]);

    unsigned v = s;
    #pragma unroll
    for (int o = 1; o < 32; o <<= 1) {
        unsigned t = __shfl_up_sync(0xFFFFFFFFu, v, o);
        if (lane >= o) v += t;
    }
    if (lane == 31) wtot[wid] = v;
    __syncthreads();

    if (wid == 0 && lane < 8) {
        unsigned t = wtot[lane];
        #pragma unroll
        for (int o = 1; o < 8; o <<= 1) {
            unsigned u = __shfl_up_sync(0xFFu, t, o);
            if (lane >= o) t += u;
        }
        wtot[lane] = t;
    }
    __syncthreads();

    unsigned excl = (wid ? wtot[wid - 1] : 0u) + (v - s);
    if (RANK0 >= excl && RANK0 < excl + s) {
        unsigned cum = excl;
        #pragma unroll 1
        for (int j = 0; j < 32; j++) {
            unsigned c = __ldcg(&h[tid * 32 + j]);
            if (RANK0 < cum + c) {
                g_d0[b] = (unsigned)(tid * 32 + j);
                g_r1[b] = RANK0 - cum;
                break;
            }
            cum += c;
        }
    }
}

// ---------------------------------------------------------------------------
// pass 1: histogram bits[17:7] among values with bits[30:18] == d0.
// PDL: smem zeroing overlaps select0; wait before reading g_d0/g_imp5.
// ---------------------------------------------------------------------------
__global__ void __launch_bounds__(256) hist1_kernel(const float4* __restrict__ coeffs) {
    __shared__ unsigned sh[NB1];
    const int tid = threadIdx.x;

    for (int i = tid; i < NB1; i += 256) sh[i] = 0;
    pdl_wait();                                  // select0 done: g_d0/g_r1 valid
    __syncthreads();

    const int batch = blockIdx.y;
    const unsigned pref = g_d0[batch];
    const int band = band_of(blockIdx.x << 4);
    const float4 imp = *reinterpret_cast<const float4*>(&g_imp5[band * HID + (tid << 2)]);
    const float4* p = coeffs + (size_t)batch * VEC_PB + (size_t)blockIdx.x * (16 * 256) + tid;

    #pragma unroll
    for (int r = 0; r < 16; r += 4) {
        float4 c0 = __ldg(p + (r + 0) * 256);
        float4 c1 = __ldg(p + (r + 1) * 256);
        float4 c2 = __ldg(p + (r + 2) * 256);
        float4 c3 = __ldg(p + (r + 3) * 256);
        unsigned bb[16];
        bb[0]  = __float_as_uint(imp.x * fabsf(c0.x));
        bb[1]  = __float_as_uint(imp.y * fabsf(c0.y));
        bb[2]  = __float_as_uint(imp.z * fabsf(c0.z));
        bb[3]  = __float_as_uint(imp.w * fabsf(c0.w));
        bb[4]  = __float_as_uint(imp.x * fabsf(c1.x));
        bb[5]  = __float_as_uint(imp.y * fabsf(c1.y));
        bb[6]  = __float_as_uint(imp.z * fabsf(c1.z));
        bb[7]  = __float_as_uint(imp.w * fabsf(c1.w));
        bb[8]  = __float_as_uint(imp.x * fabsf(c2.x));
        bb[9]  = __float_as_uint(imp.y * fabsf(c2.y));
        bb[10] = __float_as_uint(imp.z * fabsf(c2.z));
        bb[11] = __float_as_uint(imp.w * fabsf(c2.w));
        bb[12] = __float_as_uint(imp.x * fabsf(c3.x));
        bb[13] = __float_as_uint(imp.y * fabsf(c3.y));
        bb[14] = __float_as_uint(imp.z * fabsf(c3.z));
        bb[15] = __float_as_uint(imp.w * fabsf(c3.w));
        #pragma unroll
        for (int j = 0; j < 16; j++)
            if ((bb[j] >> 18) == pref) atomicAdd(&sh[(bb[j] >> 7) & (NB1 - 1)], 1u);
    }
    __syncthreads();

    unsigned* gh = g_hist1[batch];
    for (int i = tid; i < NB1; i += 256) {
        unsigned s = sh[i];
        if (s) atomicAdd(&gh[i], s);
    }
}

// ---------------------------------------------------------------------------
// select1: one warp per batch; threshold = midpoint of resolved 128-ulp bin
// (rel err <= 2^-17; measured end-to-end rel_err 5e-7).
// ---------------------------------------------------------------------------
__global__ void __launch_bounds__(256) select1_kernel() {
    pdl_wait();                                  // hist1 done: g_hist1 valid
    const int b = threadIdx.x >> 5;
    if (b >= BATCH) return;
    const int lane = threadIdx.x & 31;
    const unsigned* __restrict__ h = g_hist1[b];
    const unsigned rank = g_r1[b];

    unsigned s = 0;
    #pragma unroll
    for (int j = 0; j < 64; j++) s += __ldcg(&h[lane * 64 + j]);

    unsigned v = s;
    #pragma unroll
    for (int o = 1; o < 32; o <<= 1) {
        unsigned t = __shfl_up_sync(0xFFFFFFFFu, v, o);
        if (lane >= o) v += t;
    }
    unsigned excl = v - s;

    if (rank >= excl && rank < excl + s) {
        unsigned cum = excl;
        #pragma unroll 1
        for (int j = 0; j < 64; j++) {
            unsigned c = __ldcg(&h[lane * 64 + j]);
            if (rank < cum + c) {
                unsigned d1 = (unsigned)(lane * 64 + j);
                g_thr[b] = __uint_as_float((g_d0[b] << 18) | (d1 << 7) | 64u);
                break;
            }
            cum += c;
        }
    }
}

// ---------------------------------------------------------------------------
// final: out[0..V)=coeffs*mask, out[V..2V)=mask (importance written by hist0).
// grid (FBLK, BATCH) x 256: 8 rows/block. Streaming stores.
// PDL: wait before reading g_thr/g_imp5.
// ---------------------------------------------------------------------------
__global__ void __launch_bounds__(256) final_kernel(const float4* __restrict__ coeffs,
                                                    const float* __restrict__ temp,
                                                    float4* __restrict__ out) {
    pdl_wait();                                  // select1 done: g_thr valid
    const int tid = threadIdx.x;
    const int batch = blockIdx.y;
    const int band = band_of(blockIdx.x << 3);   // 8 rows/block
    const float4 imp = *reinterpret_cast<const float4*>(&g_imp5[band * HID + (tid << 2)]);
    const float thr = g_thr[batch];
    const float inv_t = __frcp_rn(fabsf(__ldg(&temp[0])));

    const size_t vbase = (size_t)batch * VEC_PB + (size_t)blockIdx.x * (8 * 256) + tid;
    const float4* p = coeffs + vbase;

    #pragma unroll
    for (int r = 0; r < 8; r += 2) {
        float4 c0 = __ldg(p + (r + 0) * 256);
        float4 c1 = __ldg(p + (r + 1) * 256);

        float4 mk0, fl0, mk1, fl1;
        { float ci = imp.x * fabsf(c0.x); mk0.x = sigmoidf_fast((ci - thr) * inv_t); fl0.x = c0.x * mk0.x; }
        { float ci = imp.y * fabsf(c0.y); mk0.y = sigmoidf_fast((ci - thr) * inv_t); fl0.y = c0.y * mk0.y; }
        { float ci = imp.z * fabsf(c0.z); mk0.z = sigmoidf_fast((ci - thr) * inv_t); fl0.z = c0.z * mk0.z; }
        { float ci = imp.w * fabsf(c0.w); mk0.w = sigmoidf_fast((ci - thr) * inv_t); fl0.w = c0.w * mk0.w; }
        { float ci = imp.x * fabsf(c1.x); mk1.x = sigmoidf_fast((ci - thr) * inv_t); fl1.x = c1.x * mk1.x; }
        { float ci = imp.y * fabsf(c1.y); mk1.y = sigmoidf_fast((ci - thr) * inv_t); fl1.y = c1.y * mk1.y; }
        { float ci = imp.z * fabsf(c1.z); mk1.z = sigmoidf_fast((ci - thr) * inv_t); fl1.z = c1.z * mk1.z; }
        { float ci = imp.w * fabsf(c1.w); mk1.w = sigmoidf_fast((ci - thr) * inv_t); fl1.w = c1.w * mk1.w; }

        size_t ve0 = vbase + (size_t)(r + 0) * 256;
        size_t ve1 = vbase + (size_t)(r + 1) * 256;
        __stcs(&out[ve0], fl0);
        __stcs(&out[ve1], fl1);
        __stcs(&out[TOTALV + ve0], mk0);
        __stcs(&out[TOTALV + ve1], mk1);
    }
}

// ---------------------------------------------------------------------------
// launch — PDL-chained: each dependent kernel launches early and overlaps
// its prologue with the predecessor's tail.
// ---------------------------------------------------------------------------
template <typename... Args>
static inline void launch_pdl(void (*kernel)(Args...), dim3 grid, dim3 block,
                              Args... args) {
    cudaLaunchConfig_t cfg = {};
    cfg.gridDim = grid;
    cfg.blockDim = block;
    cudaLaunchAttribute attr[1];
    attr[0].id = cudaLaunchAttributeProgrammaticStreamSerialization;
    attr[0].val.programmaticStreamSerializationAllowed = 1;
    cfg.attrs = attr;
    cfg.numAttrs = 1;
    cudaLaunchKernelEx(&cfg, kernel, args...);
}

extern "C" void kernel_launch(void* const* d_in, const int* in_sizes, int n_in,
                              void* d_out, int out_size) {
    const float* coeffs = (const float*)d_in[0];
    const float* bi     = (const float*)d_in[1];
    const float* di     = (const float*)d_in[2];
    const float* temp   = (const float*)d_in[3];
    float* out = (float*)d_out;

    setup_kernel<<<(BATCH * NB0 + 255) / 256, 256>>>(bi, di);

    dim3 hg(HBLK, BATCH);
    launch_pdl(hist0_kernel, hg, dim3(256), (const float4*)coeffs, (float4*)out);
    launch_pdl(select0_kernel, dim3(BATCH), dim3(256));
    launch_pdl(hist1_kernel, hg, dim3(256), (const float4*)coeffs);
    launch_pdl(select1_kernel, dim3(1), dim3(256));

    dim3 fg(FBLK, BATCH);
    launch_pdl(final_kernel, fg, dim3(256), (const float4*)coeffs, temp, (float4*)out);
}